// round 3
// baseline (speedup 1.0000x reference)
#include <cuda_runtime.h>
#include <cstdint>

#define BATCH 16
#define SEQ   2048
#define DIM   512
#define BD    64
#define NTOK  (BATCH*SEQ)   /* 32768 */
#define NKVQ  192

// ---------------- device scratch (no allocations allowed) ----------------
__device__ float g_Wc[DIM*NKVQ];                 // packed [Wk|Wv|Wq], 512x192
__device__ float g_bc[NKVQ];                     // packed [bk|bv|bq]
__device__ float g_KVQ[(size_t)NTOK*NKVQ];       // per-token k,v,q  (25 MB)
__device__ float g_E[NTOK];                      // per-token eta
__device__ float g_H[(size_t)NTOK*BD];           // per-token h (scan output)

// ---------------- pack kernel ----------------
__global__ void pack_kernel(const float* __restrict__ Wk, const float* __restrict__ Wv,
                            const float* __restrict__ Wq, const float* __restrict__ bk,
                            const float* __restrict__ bv, const float* __restrict__ bq)
{
    int idx = blockIdx.x*256 + threadIdx.x;
    if (idx < DIM*NKVQ){
        int k = idx / NKVQ, n = idx % NKVQ;
        float v;
        if (n < 64)       v = Wk[k*64 + n];
        else if (n < 128) v = Wv[k*64 + (n-64)];
        else              v = Wq[k*64 + (n-128)];
        g_Wc[idx] = v;
    }
    if (idx < NKVQ){
        float v;
        if (idx < 64)       v = bk[idx];
        else if (idx < 128) v = bv[idx-64];
        else                v = bq[idx-128];
        g_bc[idx] = v;
    }
}

// ---------------- fp32 GEMM body: BM=128, BN=64, BK=16, 128 thr, 8x8 tile ----------------
template<int KITERS>
__device__ __forceinline__ void gemm_body(
    const float* __restrict__ A, int lda,
    const float* __restrict__ B, int ldb,
    const float* __restrict__ bias,
    float* __restrict__ C, int ldc)
{
    __shared__ __align__(16) float As[16][128];
    __shared__ __align__(16) float Bs[16][64];

    const int tid = threadIdx.x;
    const int tx  = tid & 7;
    const int ty  = tid >> 3;
    const int mBase = blockIdx.x * 128;
    const int nBase = blockIdx.y * 64;

    const float* Ab = A + (size_t)mBase * lda;
    const float* Bb = B + nBase;

    float acc[8][8];
    #pragma unroll
    for (int i=0;i<8;i++)
        #pragma unroll
        for (int j=0;j<8;j++) acc[i][j] = 0.f;

    const int am  = tid >> 2;
    const int ak4 = tid & 3;

    for (int kt=0; kt<KITERS; kt++){
        const float* Ak = Ab + kt*16;
        const float* Bk = Bb + (size_t)kt*16*ldb;
        #pragma unroll
        for (int p=0;p<4;p++){
            int m = am + 32*p;
            float4 a = *(const float4*)(Ak + (size_t)m*lda + ak4*4);
            As[ak4*4+0][m]=a.x; As[ak4*4+1][m]=a.y; As[ak4*4+2][m]=a.z; As[ak4*4+3][m]=a.w;
        }
        #pragma unroll
        for (int p=0;p<2;p++){
            int id = tid + 128*p;
            int r = id >> 4, c4 = id & 15;
            *(float4*)(&Bs[r][c4*4]) = *(const float4*)(Bk + (size_t)r*ldb + c4*4);
        }
        __syncthreads();
        #pragma unroll
        for (int kk=0; kk<16; kk++){
            float4 a0 = *(const float4*)(&As[kk][ty*8]);
            float4 a1 = *(const float4*)(&As[kk][ty*8+4]);
            float4 b0 = *(const float4*)(&Bs[kk][tx*8]);
            float4 b1 = *(const float4*)(&Bs[kk][tx*8+4]);
            float av[8] = {a0.x,a0.y,a0.z,a0.w,a1.x,a1.y,a1.z,a1.w};
            float bw[8] = {b0.x,b0.y,b0.z,b0.w,b1.x,b1.y,b1.z,b1.w};
            #pragma unroll
            for (int i=0;i<8;i++)
                #pragma unroll
                for (int j=0;j<8;j++)
                    acc[i][j] = fmaf(av[i], bw[j], acc[i][j]);
        }
        __syncthreads();
    }

    float bvc[8];
    #pragma unroll
    for (int j=0;j<8;j++) bvc[j] = bias[nBase + tx*8 + j];
    #pragma unroll
    for (int i=0;i<8;i++){
        int row = mBase + ty*8 + i;
        float4 o0 = make_float4(acc[i][0]+bvc[0], acc[i][1]+bvc[1],
                                acc[i][2]+bvc[2], acc[i][3]+bvc[3]);
        float4 o1 = make_float4(acc[i][4]+bvc[4], acc[i][5]+bvc[5],
                                acc[i][6]+bvc[6], acc[i][7]+bvc[7]);
        *(float4*)(C + (size_t)row*ldc + nBase + tx*8)     = o0;
        *(float4*)(C + (size_t)row*ldc + nBase + tx*8 + 4) = o1;
    }
}

__global__ void __launch_bounds__(128) gemm1_kernel(const float* __restrict__ x){
    gemm_body<32>(x, DIM, g_Wc, NKVQ, g_bc, g_KVQ, NKVQ);
}
__global__ void __launch_bounds__(128) gemm3_kernel(const float* __restrict__ Wo,
                                                    const float* __restrict__ bo,
                                                    float* __restrict__ out){
    gemm_body<4>(g_H, BD, Wo, DIM, bo, out, DIM);
}

// ---------------- eta kernel ----------------
__global__ void eta_kernel(const float* __restrict__ x,
                           const float* __restrict__ lrw,
                           const float* __restrict__ lrb)
{
    int warp = threadIdx.x >> 5, lane = threadIdx.x & 31;
    int row = blockIdx.x*8 + warp;
    const float* xr = x + (size_t)row*DIM;
    float s = 0.f;
    #pragma unroll
    for (int j=0;j<16;j++) s = fmaf(xr[lane + 32*j], lrw[lane + 32*j], s);
    #pragma unroll
    for (int d=16; d; d>>=1) s += __shfl_xor_sync(0xffffffffu, s, d);
    if (lane == 0){
        float raw = s + lrb[0];
        g_E[row] = 1.f/(1.f + expf(-raw));
    }
}

// ---------------- sequential scan: one CTA per batch, W in registers ----------------
// thread t: o = t>>1 owns W row o; half = t&1 owns cols [32*half, 32*half+32)
// Single merged reduction round per token: dh = a + G*hat decomposition lets all
// LN-backward statistics be expressed via 18 sums of products of {u,u2,a,G,k,q}.
__global__ void __launch_bounds__(128, 1) scan_kernel(
    const float* __restrict__ W0,
    const float* __restrict__ ln_g,
    const float* __restrict__ ln_b)
{
    __shared__ __align__(16) float sKVQ[2][192];   // [k(64)|v(64)|q(64)], double-buffered
    __shared__ float sE[2];
    __shared__ float sG[64], sB[64];
    __shared__ __align__(16) float red[2][18][4];  // [parity][quantity][warp]

    const int tid  = threadIdx.x;
    const int o    = tid >> 1;
    const int half = tid & 1;
    const int cb   = half << 5;
    const int warp = tid >> 5, lane = tid & 31;
    const int b    = blockIdx.x;

    float w[32];
    #pragma unroll
    for (int j=0;j<32;j++) w[j] = W0[o*64 + cb + j];
    if (tid < 64){ sG[tid] = ln_g[tid]; sB[tid] = ln_b[tid]; }
    __syncthreads();

    const float inv = 1.f/64.f;
    const float s2  = 2.f/64.f;

    // constants: G_o = (2/64) g_o^2 ; EG = mean(G), EG2 = mean(G^2)
    float go  = sG[o];
    float lbo = sB[o];
    float Gc  = s2*go*go;
    float EG = 0.f, EG2 = 0.f;
    #pragma unroll 8
    for (int j=0;j<64;j++){
        float gj = sG[j]; float Gj = s2*gj*gj;
        EG += Gj; EG2 += Gj*Gj;
    }
    EG *= inv; EG2 *= inv;

    const float* kvq   = g_KVQ + (size_t)b*SEQ*192;
    const float* ebase = g_E + b*SEQ;
    float*       hbase = g_H + (size_t)b*SEQ*64;

    float4 pre = make_float4(0.f,0.f,0.f,0.f);
    float preE = 0.f;
    if (tid < 48) pre = *(const float4*)(kvq + tid*4);
    if (tid == 0) preE = ebase[0];
    if (tid < 48) *(float4*)(&sKVQ[0][tid*4]) = pre;
    if (tid == 0) sE[0] = preE;
    __syncthreads();

    for (int t=0; t<SEQ; t++){
        const int p = t & 1;
        // prefetch next token into registers (hides L2 latency under the chain)
        if (t+1 < SEQ){
            if (tid < 48) pre = *(const float4*)(kvq + (size_t)(t+1)*192 + tid*4);
            if (tid == 0) preE = ebase[t+1];
        }
        const float* ks = &sKVQ[p][0];
        const float* vs = &sKVQ[p][64];
        const float* qs = &sKVQ[p][128];

        // half-matvecs: u = W k, u2 = W q
        float ua=0.f, ub=0.f, ya=0.f, yb=0.f;
        #pragma unroll
        for (int j4=0; j4<8; j4++){
            float4 kk = *(const float4*)(ks + cb + j4*4);
            float4 qq = *(const float4*)(qs + cb + j4*4);
            ua = fmaf(w[j4*4+0], kk.x, ua);
            ub = fmaf(w[j4*4+1], kk.y, ub);
            ua = fmaf(w[j4*4+2], kk.z, ua);
            ub = fmaf(w[j4*4+3], kk.w, ub);
            ya = fmaf(w[j4*4+0], qq.x, ya);
            yb = fmaf(w[j4*4+1], qq.y, yb);
            ya = fmaf(w[j4*4+2], qq.z, ya);
            yb = fmaf(w[j4*4+3], qq.w, yb);
        }
        float up = ua + ub, u2p = ya + yb;
        float u  = up  + __shfl_xor_sync(0xffffffffu, up, 1);
        float u2 = u2p + __shfl_xor_sync(0xffffffffu, u2p, 1);

        float ko = ks[o], vo = vs[o], qo = qs[o];
        float a  = s2*go*(ko + lbo - vo);     // dL/dhat = a + G*hat

        // 9 local quantities per thread, split by parity (pair threads are redundant:
        // both hold identical per-o values, so same-parity lanes cover each o once)
        float r[9];
        if (!half){
            r[0]=u;      r[1]=u*u;    r[2]=u2;     r[3]=u2*u2; r[4]=u*u2;
            r[5]=ko*qo;  r[6]=a;      r[7]=a*u;    r[8]=a*u2;
        } else {
            float G2 = Gc*Gc;
            r[0]=a*a;    r[1]=Gc*u;   r[2]=Gc*u*u; r[3]=Gc*u*u2; r[4]=Gc*u2;
            r[5]=a*Gc;   r[6]=a*Gc*u; r[7]=G2*u;   r[8]=G2*u*u;
        }
        // 4-round xor reduction over same-parity lanes (d = 16,8,4,2)
        #pragma unroll
        for (int d=16; d>1; d>>=1){
            #pragma unroll
            for (int j=0;j<9;j++) r[j] += __shfl_xor_sync(0xffffffffu, r[j], d);
        }
        if (lane == 0){
            #pragma unroll
            for (int j=0;j<9;j++) red[p][j][warp] = r[j];
        } else if (lane == 1){
            #pragma unroll
            for (int j=0;j<9;j++) red[p][9+j][warp] = r[j];
        }

        // stage next token before the (single) barrier
        if (t+1 < SEQ){
            if (tid < 48) *(float4*)(&sKVQ[p^1][tid*4]) = pre;
            if (tid == 0) sE[p^1] = preE;
        }
        __syncthreads();

        // cross-warp combine (broadcast LDS, conflict-free)
        float S[18];
        #pragma unroll
        for (int j=0;j<18;j++){
            float4 rr = *(const float4*)red[p][j];
            S[j] = (rr.x+rr.y)+(rr.z+rr.w);
        }
        float Su=S[0], Suu=S[1], Su2=S[2], Su2sq=S[3], Suu2=S[4], Skq=S[5];
        float Sa=S[6], Sau=S[7], Sau2=S[8];
        float Sa2=S[9], SGu=S[10], SGuu=S[11], SGuu2=S[12], SGu2=S[13];
        float SaG=S[14], SaGu=S[15], SG2u=S[16], SG2uu=S[17];

        float mu   = Su*inv;
        float var  = Suu*inv - mu*mu;
        float rstd = rsqrtf(var + 1e-6f);
        float rstd2 = rstd*rstd;

        float Ea=Sa*inv, Eau=Sau*inv, Eau2=Sau2*inv, Ea2=Sa2*inv;
        float EGu=SGu*inv, EGuu=SGuu*inv, EGuu2=SGuu2*inv, EGu2=SGu2*inv;
        float EaG=SaG*inv, EaGu=SaGu*inv, EG2u=SG2u*inv, EG2uu=SG2uu*inv;
        float Eu2=Su2*inv, Eu2sq=Su2sq*inv, Euu2=Suu2*inv;

        float m1 = Ea + rstd*(EGu - mu*EG);
        float m2 = rstd*(Eau - mu*Ea)
                 + rstd2*(EGuu - 2.f*mu*EGu + mu*mu*EG);
        float mean_u2hat = rstd*(Euu2 - mu*Eu2);
        float mean_u2dh  = Eau2 + rstd*(EGuu2 - mu*EGu2);
        float mean_dh2   = Ea2 + 2.f*rstd*(EaGu - mu*EaG)
                         + rstd2*(EG2uu - 2.f*mu*EG2u + mu*mu*EG2);
        float R = var*rstd2;
        float mean_u2du = rstd*(mean_u2dh - m1*Eu2 - m2*mean_u2hat);
        float mean_du2  = rstd2*(mean_dh2 - m1*m1 + m2*m2*(R - 2.f));

        float eta = sE[p];
        float c = eta*Skq;
        float mean_y = Eu2;                   // mean(du) == 0 analytically
        float var_y  = Eu2sq - 2.f*c*mean_u2du + c*c*mean_du2 - mean_y*mean_y;
        float rstdy  = rsqrtf(var_y + 1e-6f);

        float hat = (u - mu)*rstd;
        float dh  = a + Gc*hat;
        float du  = rstd*(dh - m1 - hat*m2);
        float y   = u2 - c*du;                // W_new @ q
        float h   = qo + (y - mean_y)*rstdy*go + lbo;
        if (!half) hbase[(size_t)t*64 + o] = h;

        // rank-1 W update: W -= eta * du (x) k
        float coef = eta*du;
        #pragma unroll
        for (int j4=0;j4<8;j4++){
            float4 kk = *(const float4*)(ks + cb + j4*4);
            w[j4*4+0] = fmaf(-coef, kk.x, w[j4*4+0]);
            w[j4*4+1] = fmaf(-coef, kk.y, w[j4*4+1]);
            w[j4*4+2] = fmaf(-coef, kk.z, w[j4*4+2]);
            w[j4*4+3] = fmaf(-coef, kk.w, w[j4*4+3]);
        }
    }
}

// ---------------- launch ----------------
extern "C" void kernel_launch(void* const* d_in, const int* in_sizes, int n_in,
                              void* d_out, int out_size)
{
    const float* x   = (const float*)d_in[0];
    const float* Wk  = (const float*)d_in[1];
    const float* bk  = (const float*)d_in[2];
    const float* Wv  = (const float*)d_in[3];
    const float* bv  = (const float*)d_in[4];
    const float* Wq  = (const float*)d_in[5];
    const float* bq  = (const float*)d_in[6];
    const float* Wo  = (const float*)d_in[7];
    const float* bo  = (const float*)d_in[8];
    const float* lng = (const float*)d_in[9];
    const float* lnb = (const float*)d_in[10];
    const float* lrw = (const float*)d_in[11];
    const float* lrb = (const float*)d_in[12];
    const float* W0  = (const float*)d_in[13];
    float* out = (float*)d_out;

    pack_kernel<<<(DIM*NKVQ + 255)/256, 256>>>(Wk, Wv, Wq, bk, bv, bq);
    gemm1_kernel<<<dim3(NTOK/128, 3), 128>>>(x);
    eta_kernel<<<NTOK/8, 256>>>(x, lrw, lrb);
    scan_kernel<<<BATCH, 128>>>(W0, lng, lnb);
    gemm3_kernel<<<dim3(NTOK/128, 8), 128>>>(Wo, bo, out);
}

// round 4
// speedup vs baseline: 1.1890x; 1.1890x over previous
#include <cuda_runtime.h>
#include <cstdint>

#define BATCH 16
#define SEQ   2048
#define DIM   512
#define BD    64
#define NTOK  (BATCH*SEQ)   /* 32768 */
#define NKVQ  192

// ---------------- device scratch ----------------
__device__ float g_Wc[DIM*NKVQ];                 // packed [Wk|Wv|Wq]
__device__ float g_bc[NKVQ];
__device__ float g_KVQ[(size_t)NTOK*NKVQ];       // per-token k,v,q
__device__ float g_E[NTOK];                      // eta
__device__ float g_SC[(size_t)NTOK*8];           // per-token scalars {eta,kk,kq,Skq,Ea,Ea2,EaG,0}
__device__ float g_H[(size_t)NTOK*BD];           // scan output h

// ---------------- pack ----------------
__global__ void pack_kernel(const float* __restrict__ Wk, const float* __restrict__ Wv,
                            const float* __restrict__ Wq, const float* __restrict__ bk,
                            const float* __restrict__ bv, const float* __restrict__ bq)
{
    int idx = blockIdx.x*256 + threadIdx.x;
    if (idx < DIM*NKVQ){
        int k = idx / NKVQ, n = idx % NKVQ;
        float v;
        if (n < 64)       v = Wk[k*64 + n];
        else if (n < 128) v = Wv[k*64 + (n-64)];
        else              v = Wq[k*64 + (n-128)];
        g_Wc[idx] = v;
    }
    if (idx < NKVQ){
        float v;
        if (idx < 64)       v = bk[idx];
        else if (idx < 128) v = bv[idx-64];
        else                v = bq[idx-128];
        g_bc[idx] = v;
    }
}

// ---------------- fp32 GEMM body ----------------
template<int KITERS>
__device__ __forceinline__ void gemm_body(
    const float* __restrict__ A, int lda,
    const float* __restrict__ B, int ldb,
    const float* __restrict__ bias,
    float* __restrict__ C, int ldc)
{
    __shared__ __align__(16) float As[16][128];
    __shared__ __align__(16) float Bs[16][64];

    const int tid = threadIdx.x;
    const int tx  = tid & 7;
    const int ty  = tid >> 3;
    const int mBase = blockIdx.x * 128;
    const int nBase = blockIdx.y * 64;

    const float* Ab = A + (size_t)mBase * lda;
    const float* Bb = B + nBase;

    float acc[8][8];
    #pragma unroll
    for (int i=0;i<8;i++)
        #pragma unroll
        for (int j=0;j<8;j++) acc[i][j] = 0.f;

    const int am  = tid >> 2;
    const int ak4 = tid & 3;

    for (int kt=0; kt<KITERS; kt++){
        const float* Ak = Ab + kt*16;
        const float* Bk = Bb + (size_t)kt*16*ldb;
        #pragma unroll
        for (int p=0;p<4;p++){
            int m = am + 32*p;
            float4 a = *(const float4*)(Ak + (size_t)m*lda + ak4*4);
            As[ak4*4+0][m]=a.x; As[ak4*4+1][m]=a.y; As[ak4*4+2][m]=a.z; As[ak4*4+3][m]=a.w;
        }
        #pragma unroll
        for (int p=0;p<2;p++){
            int id = tid + 128*p;
            int r = id >> 4, c4 = id & 15;
            *(float4*)(&Bs[r][c4*4]) = *(const float4*)(Bk + (size_t)r*ldb + c4*4);
        }
        __syncthreads();
        #pragma unroll
        for (int kk=0; kk<16; kk++){
            float4 a0 = *(const float4*)(&As[kk][ty*8]);
            float4 a1 = *(const float4*)(&As[kk][ty*8+4]);
            float4 b0 = *(const float4*)(&Bs[kk][tx*8]);
            float4 b1 = *(const float4*)(&Bs[kk][tx*8+4]);
            float av[8] = {a0.x,a0.y,a0.z,a0.w,a1.x,a1.y,a1.z,a1.w};
            float bw[8] = {b0.x,b0.y,b0.z,b0.w,b1.x,b1.y,b1.z,b1.w};
            #pragma unroll
            for (int i=0;i<8;i++)
                #pragma unroll
                for (int j=0;j<8;j++)
                    acc[i][j] = fmaf(av[i], bw[j], acc[i][j]);
        }
        __syncthreads();
    }

    float bvc[8];
    #pragma unroll
    for (int j=0;j<8;j++) bvc[j] = bias[nBase + tx*8 + j];
    #pragma unroll
    for (int i=0;i<8;i++){
        int row = mBase + ty*8 + i;
        float4 o0 = make_float4(acc[i][0]+bvc[0], acc[i][1]+bvc[1],
                                acc[i][2]+bvc[2], acc[i][3]+bvc[3]);
        float4 o1 = make_float4(acc[i][4]+bvc[4], acc[i][5]+bvc[5],
                                acc[i][6]+bvc[6], acc[i][7]+bvc[7]);
        *(float4*)(C + (size_t)row*ldc + nBase + tx*8)     = o0;
        *(float4*)(C + (size_t)row*ldc + nBase + tx*8 + 4) = o1;
    }
}

__global__ void __launch_bounds__(128) gemm1_kernel(const float* __restrict__ x){
    gemm_body<32>(x, DIM, g_Wc, NKVQ, g_bc, g_KVQ, NKVQ);
}
__global__ void __launch_bounds__(128) gemm3_kernel(const float* __restrict__ Wo,
                                                    const float* __restrict__ bo,
                                                    float* __restrict__ out){
    gemm_body<4>(g_H, BD, Wo, DIM, bo, out, DIM);
}

// ---------------- eta ----------------
__global__ void eta_kernel(const float* __restrict__ x,
                           const float* __restrict__ lrw,
                           const float* __restrict__ lrb)
{
    int warp = threadIdx.x >> 5, lane = threadIdx.x & 31;
    int row = blockIdx.x*8 + warp;
    const float* xr = x + (size_t)row*DIM;
    float s = 0.f;
    #pragma unroll
    for (int j=0;j<16;j++) s = fmaf(xr[lane + 32*j], lrw[lane + 32*j], s);
    #pragma unroll
    for (int d=16; d; d>>=1) s += __shfl_xor_sync(0xffffffffu, s, d);
    if (lane == 0){
        float raw = s + lrb[0];
        g_E[row] = 1.f/(1.f + expf(-raw));
    }
}

// ---------------- prep: per-token data-only scalars ----------------
// writes {eta, kk=k_{t-1}.k_t, kq=k_{t-1}.q_t, Skq=k_t.q_t, Ea, Ea2, EaG, 0}
__global__ void prep_kernel(const float* __restrict__ lng, const float* __restrict__ lnb)
{
    int warp = threadIdx.x >> 5, lane = threadIdx.x & 31;
    int tok = blockIdx.x*8 + warp;
    int t = tok & (SEQ-1);
    const float* base = g_KVQ + (size_t)tok*192;
    float k0=base[lane],     k1=base[lane+32];
    float v0=base[64+lane],  v1=base[96+lane];
    float q0=base[128+lane], q1=base[160+lane];
    float km0=0.f, km1=0.f;
    if (t > 0){ km0 = base[lane-192]; km1 = base[lane+32-192]; }
    float g0=lng[lane], g1=lng[lane+32];
    float b0=lnb[lane], b1=lnb[lane+32];
    const float s2 = 2.f/64.f, inv = 1.f/64.f;
    float a0=s2*g0*(k0+b0-v0), a1=s2*g1*(k1+b1-v1);
    float G0=s2*g0*g0, G1=s2*g1*g1;
    float r0=k0*q0 + k1*q1;     // Skq
    float r1=km0*k0 + km1*k1;   // kk
    float r2=km0*q0 + km1*q1;   // kq
    float r3=a0+a1;             // Sa
    float r4=a0*a0 + a1*a1;     // Sa2
    float r5=a0*G0 + a1*G1;     // SaG
    #pragma unroll
    for (int d=16; d; d>>=1){
        r0+=__shfl_xor_sync(0xffffffffu,r0,d);
        r1+=__shfl_xor_sync(0xffffffffu,r1,d);
        r2+=__shfl_xor_sync(0xffffffffu,r2,d);
        r3+=__shfl_xor_sync(0xffffffffu,r3,d);
        r4+=__shfl_xor_sync(0xffffffffu,r4,d);
        r5+=__shfl_xor_sync(0xffffffffu,r5,d);
    }
    if (lane == 0){
        float* sc = g_SC + (size_t)tok*8;
        *(float4*)(sc)   = make_float4(g_E[tok], r1, r2, r0);
        *(float4*)(sc+4) = make_float4(r3*inv, r4*inv, r5*inv, 0.f);
    }
}

// ---------------- sequential scan with rank-1 look-ahead ----------------
// thread t: o = tid>>1; half = tid&1 owns W[o][32*half..+32)
// Recurrence propagates only through du; matvec p_{t+1}=W_t k_{t+1} and W update
// run off-chain inside the shuffle-latency shadow.
__global__ void __launch_bounds__(128, 1) scan_kernel(
    const float* __restrict__ W0,
    const float* __restrict__ ln_g,
    const float* __restrict__ ln_b)
{
    __shared__ __align__(16) float sTok[4][200];   // ring: [k64|v64|q64|sc8]
    __shared__ float sG[64], sB[64];
    __shared__ __align__(16) float red[2][14][4];  // [parity][qty][warp]

    const int tid=threadIdx.x, o=tid>>1, half=tid&1, cb=half<<5;
    const int warp=tid>>5, lane=tid&31, b=blockIdx.x;

    float w[32];
    #pragma unroll
    for (int j=0;j<32;j++) w[j] = W0[o*64 + cb + j];
    if (tid < 64){ sG[tid]=ln_g[tid]; sB[tid]=ln_b[tid]; }
    if (tid < 50) *(float4*)(&sTok[3][tid*4]) = make_float4(0.f,0.f,0.f,0.f);

    const float* kvq = g_KVQ + (size_t)b*SEQ*192;
    const float* scb = g_SC  + (size_t)b*SEQ*8;
    float*       hbase = g_H + (size_t)b*SEQ*64;

    // preamble: tokens 0,1 -> slots 0,1; pre4 = token 2
    float4 pre4 = make_float4(0.f,0.f,0.f,0.f);
    {
        float4 t0 = pre4, t1 = pre4;
        if (tid < 48){
            t0 = *(const float4*)(kvq + tid*4);
            t1 = *(const float4*)(kvq + 192 + tid*4);
            pre4 = *(const float4*)(kvq + 2*192 + tid*4);
        } else if (tid < 50){
            int j = (tid-48)*4;
            t0 = *(const float4*)(scb + j);
            t1 = *(const float4*)(scb + 8 + j);
            pre4 = *(const float4*)(scb + 16 + j);
        }
        if (tid < 48){
            *(float4*)(&sTok[0][tid*4]) = t0;
            *(float4*)(&sTok[1][tid*4]) = t1;
        } else if (tid < 50){
            int j = 192 + (tid-48)*4;
            *(float4*)(&sTok[0][j]) = t0;
            *(float4*)(&sTok[1][j]) = t1;
        }
    }
    __syncthreads();

    const float inv = 1.f/64.f, s2 = 2.f/64.f;
    const float go = sG[o], lbo = sB[o];
    const float Gc = s2*go*go, G2 = Gc*Gc;
    float EG=0.f, EG2=0.f;
    #pragma unroll 8
    for (int j=0;j<64;j++){ float gj=sG[j]; float Gj=s2*gj*gj; EG+=Gj; EG2+=Gj*Gj; }
    EG*=inv; EG2*=inv;

    // bootstrap: p, p2 for token 0
    float p, p2;
    {
        float pa=0.f, pb=0.f;
        #pragma unroll
        for (int j4=0;j4<8;j4++){
            float4 kk=*(const float4*)(&sTok[0][cb+j4*4]);
            float4 qq=*(const float4*)(&sTok[0][128+cb+j4*4]);
            pa=fmaf(w[j4*4+0],kk.x,pa); pa=fmaf(w[j4*4+1],kk.y,pa);
            pa=fmaf(w[j4*4+2],kk.z,pa); pa=fmaf(w[j4*4+3],kk.w,pa);
            pb=fmaf(w[j4*4+0],qq.x,pb); pb=fmaf(w[j4*4+1],qq.y,pb);
            pb=fmaf(w[j4*4+2],qq.z,pb); pb=fmaf(w[j4*4+3],qq.w,pb);
        }
        p  = pa + __shfl_xor_sync(0xffffffffu, pa, 1);
        p2 = pb + __shfl_xor_sync(0xffffffffu, pb, 1);
    }
    float ko=sTok[0][o], vo=sTok[0][64+o], qo=sTok[0][128+o];
    float a = s2*go*(ko+lbo-vo), aG = a*Gc;
    float etaCur = sTok[0][192+0];
    float c      = etaCur*sTok[0][192+3];
    float Ea=sTok[0][192+4], Ea2=sTok[0][192+5], EaG=sTok[0][192+6];
    float cc1=0.f, cc2=0.f, du_prev=0.f, coef_prev=0.f;

    for (int t=0; t<SEQ; t++){
        const int pr = t&1;
        const float* prv = sTok[(t+3)&3];
        const float* nxt = sTok[(t+1)&3];
        float*       stg = sTok[(t+2)&3];

        // CRITICAL: correction from previous du
        float u  = fmaf(-cc1, du_prev, p);
        float u2 = fmaf(-cc2, du_prev, p2);

        // parity-packed stats: even lanes carry critical, odd lanes secondary
        float r0,r1,r2,r3,r4,r5,r6;
        if (!half){
            r0=u; r1=u*u; r2=Gc*u; r3=Gc*u*u; r4=a*u; r5=aG*u; r6=G2*u;
        } else {
            r0=u2; r1=u2*u2; r2=u*u2; r3=Gc*u2; r4=Gc*u*u2; r5=a*u2; r6=G2*u*u;
        }
        #pragma unroll
        for (int d=16; d>1; d>>=1){
            r0+=__shfl_xor_sync(0xffffffffu,r0,d);
            r1+=__shfl_xor_sync(0xffffffffu,r1,d);
            r2+=__shfl_xor_sync(0xffffffffu,r2,d);
            r3+=__shfl_xor_sync(0xffffffffu,r3,d);
            r4+=__shfl_xor_sync(0xffffffffu,r4,d);
            r5+=__shfl_xor_sync(0xffffffffu,r5,d);
            r6+=__shfl_xor_sync(0xffffffffu,r6,d);
        }

        // OFF-CHAIN (fills shuffle shadow): W += -coef_prev * k_{t-1}; p_{t+1} = W_t k_{t+1}
        float pa=0.f, pb=0.f;
        #pragma unroll
        for (int j4=0;j4<8;j4++){
            float4 kp=*(const float4*)(prv + cb + j4*4);
            w[j4*4+0]=fmaf(-coef_prev,kp.x,w[j4*4+0]);
            w[j4*4+1]=fmaf(-coef_prev,kp.y,w[j4*4+1]);
            w[j4*4+2]=fmaf(-coef_prev,kp.z,w[j4*4+2]);
            w[j4*4+3]=fmaf(-coef_prev,kp.w,w[j4*4+3]);
        }
        #pragma unroll
        for (int j4=0;j4<8;j4++){
            float4 kn=*(const float4*)(nxt + cb + j4*4);
            float4 qn=*(const float4*)(nxt + 128 + cb + j4*4);
            pa=fmaf(w[j4*4+0],kn.x,pa); pa=fmaf(w[j4*4+1],kn.y,pa);
            pa=fmaf(w[j4*4+2],kn.z,pa); pa=fmaf(w[j4*4+3],kn.w,pa);
            pb=fmaf(w[j4*4+0],qn.x,pb); pb=fmaf(w[j4*4+1],qn.y,pb);
            pb=fmaf(w[j4*4+2],qn.z,pb); pb=fmaf(w[j4*4+3],qn.w,pb);
        }
        float pn  = pa + __shfl_xor_sync(0xffffffffu, pa, 1);
        float p2n = pb + __shfl_xor_sync(0xffffffffu, pb, 1);

        if (lane == 0){
            red[pr][0][warp]=r0; red[pr][1][warp]=r1; red[pr][2][warp]=r2;
            red[pr][3][warp]=r3; red[pr][4][warp]=r4; red[pr][5][warp]=r5;
            red[pr][6][warp]=r6;
        } else if (lane == 1){
            red[pr][7][warp]=r0;  red[pr][8][warp]=r1;  red[pr][9][warp]=r2;
            red[pr][10][warp]=r3; red[pr][11][warp]=r4; red[pr][12][warp]=r5;
            red[pr][13][warp]=r6;
        }
        if (t+2 < SEQ){
            if (tid < 48) *(float4*)(&stg[tid*4]) = pre4;
            else if (tid < 50) *(float4*)(&stg[192+(tid-48)*4]) = pre4;
        }
        __syncthreads();

        // prefetch token t+3 (hidden, used next iter)
        if (t+3 < SEQ){
            if (tid < 48) pre4 = *(const float4*)(kvq + (size_t)(t+3)*192 + tid*4);
            else if (tid < 50) pre4 = *(const float4*)(scb + (size_t)(t+3)*8 + (tid-48)*4);
        }

        // CRITICAL: cross-warp combine + scalar chain -> du
        float4 x0=*(const float4*)red[pr][0];
        float4 x1=*(const float4*)red[pr][1];
        float4 x2=*(const float4*)red[pr][2];
        float4 x3=*(const float4*)red[pr][3];
        float4 x4=*(const float4*)red[pr][4];
        float Su  =(x0.x+x0.y)+(x0.z+x0.w);
        float Suu =(x1.x+x1.y)+(x1.z+x1.w);
        float SGu =(x2.x+x2.y)+(x2.z+x2.w);
        float SGuu=(x3.x+x3.y)+(x3.z+x3.w);
        float Sau =(x4.x+x4.y)+(x4.z+x4.w);

        float mu   = Su*inv;
        float var  = Suu*inv - mu*mu;
        float rstd = rsqrtf(var + 1e-6f);
        float rstd2= rstd*rstd;
        float EGu=SGu*inv, EGuu=SGuu*inv, Eau=Sau*inv;
        float m1 = Ea + rstd*(EGu - mu*EG);
        float m2 = rstd*(Eau - mu*Ea) + rstd2*(EGuu - 2.f*mu*EGu + mu*mu*EG);
        float hat = (u - mu)*rstd;
        float dh  = a + Gc*hat;
        float du  = rstd*(dh - m1 - hat*m2);

        // OFF-CHAIN: h output (secondary sums)
        float4 x5=*(const float4*)red[pr][5];
        float4 x6=*(const float4*)red[pr][6];
        float4 y0=*(const float4*)red[pr][7];
        float4 y1=*(const float4*)red[pr][8];
        float4 y2=*(const float4*)red[pr][9];
        float4 y3=*(const float4*)red[pr][10];
        float4 y4=*(const float4*)red[pr][11];
        float4 y5=*(const float4*)red[pr][12];
        float4 y6=*(const float4*)red[pr][13];
        float EaGu =((x5.x+x5.y)+(x5.z+x5.w))*inv;
        float EG2u =((x6.x+x6.y)+(x6.z+x6.w))*inv;
        float Eu2  =((y0.x+y0.y)+(y0.z+y0.w))*inv;
        float Eu2sq=((y1.x+y1.y)+(y1.z+y1.w))*inv;
        float Euu2 =((y2.x+y2.y)+(y2.z+y2.w))*inv;
        float EGu2 =((y3.x+y3.y)+(y3.z+y3.w))*inv;
        float EGuu2=((y4.x+y4.y)+(y4.z+y4.w))*inv;
        float Eau2 =((y5.x+y5.y)+(y5.z+y5.w))*inv;
        float EG2uu=((y6.x+y6.y)+(y6.z+y6.w))*inv;

        float mean_u2hat = rstd*(Euu2 - mu*Eu2);
        float mean_u2dh  = Eau2 + rstd*(EGuu2 - mu*EGu2);
        float mean_u2du  = rstd*(mean_u2dh - m1*Eu2 - m2*mean_u2hat);
        float mean_dh2   = Ea2 + 2.f*rstd*(EaGu - mu*EaG)
                         + rstd2*(EG2uu - 2.f*mu*EG2u + mu*mu*EG2);
        float R = var*rstd2;
        float mean_du2 = rstd2*(mean_dh2 - m1*m1 + m2*m2*(R - 2.f));
        float var_y = Eu2sq - 2.f*c*mean_u2du + c*c*mean_du2 - Eu2*Eu2;
        float rstdy = rsqrtf(var_y + 1e-6f);
        float y  = u2 - c*du;
        float h  = qo + (y - Eu2)*rstdy*go + lbo;
        if (!half) hbase[(size_t)t*64 + o] = h;

        // advance recurrence state
        du_prev   = du;
        coef_prev = etaCur*du;
        p = pn; p2 = p2n;
        if (t+1 < SEQ){
            ko = nxt[o]; vo = nxt[64+o]; qo = nxt[128+o];
            a  = s2*go*(ko + lbo - vo); aG = a*Gc;
            float etaN = nxt[192+0];
            cc1 = etaCur*nxt[192+1];
            cc2 = etaCur*nxt[192+2];
            c   = etaN*nxt[192+3];
            Ea  = nxt[192+4]; Ea2 = nxt[192+5]; EaG = nxt[192+6];
            etaCur = etaN;
        }
    }
}

// ---------------- launch ----------------
extern "C" void kernel_launch(void* const* d_in, const int* in_sizes, int n_in,
                              void* d_out, int out_size)
{
    const float* x   = (const float*)d_in[0];
    const float* Wk  = (const float*)d_in[1];
    const float* bk  = (const float*)d_in[2];
    const float* Wv  = (const float*)d_in[3];
    const float* bv  = (const float*)d_in[4];
    const float* Wq  = (const float*)d_in[5];
    const float* bq  = (const float*)d_in[6];
    const float* Wo  = (const float*)d_in[7];
    const float* bo  = (const float*)d_in[8];
    const float* lng = (const float*)d_in[9];
    const float* lnb = (const float*)d_in[10];
    const float* lrw = (const float*)d_in[11];
    const float* lrb = (const float*)d_in[12];
    const float* W0  = (const float*)d_in[13];
    float* out = (float*)d_out;

    pack_kernel<<<(DIM*NKVQ + 255)/256, 256>>>(Wk, Wv, Wq, bk, bv, bq);
    gemm1_kernel<<<dim3(NTOK/128, 3), 128>>>(x);
    eta_kernel<<<NTOK/8, 256>>>(x, lrw, lrb);
    prep_kernel<<<NTOK/8, 256>>>(lng, lnb);
    scan_kernel<<<BATCH, 128>>>(W0, lng, lnb);
    gemm3_kernel<<<dim3(NTOK/128, 8), 128>>>(Wo, bo, out);
}